// round 15
// baseline (speedup 1.0000x reference)
#include <cuda_runtime.h>
#include <cstdint>
#include <math.h>

// Problem-size constants (fixed by the dataset)
#define NN   50000
#define EMAX 800000
#define PMAX 200000
#define SCB  512                    // scan block size
#define NSB  ((NN + SCB - 1) / SCB) // number of scan blocks (98)

// ---------------- scratch (device globals; no runtime allocation) ----------------
__device__ __align__(16) float g_h1[NN * 128];   // x @ W1
__device__ __align__(16) float g_z1[NN * 128];   // relu(agg(h1) + b1)
__device__ __align__(16) float g_h2[NN * 64];    // z1 @ W2
__device__ __align__(16) float g_z2[NN * 64];    // agg(h2) + b2
__device__ __align__(16) float g_u [NN * 128];   // z2 @ Wa[0:64]  + ba
__device__ __align__(16) float g_v [NN * 128];   // z2 @ Wa[64:128]
__device__ __align__(16) float g_pp[2 * PMAX];   // decode partial sums
__device__ __align__(16) float g_dinv[NN];
__device__ __align__(16) int   g_cnt [NN];
__device__ __align__(16) int   g_fill[NN];
__device__ __align__(16) int   g_rowptr[NN + 1];
__device__ __align__(16) int   g_col[EMAX];
__device__ __align__(16) int   g_bsum[NSB + 1];
__device__ int g_is64;   // 1 if index arrays are int64, 0 if int32

// packed fp32x2 FMA: d = a*b + d (elementwise on 64-bit register pairs)
#define FMA_F32X2(d, a, b) \
    asm("fma.rn.f32x2 %0, %1, %2, %0;" : "+l"(d) : "l"(a), "l"(b))
// pack one float into both halves of a 64-bit register pair (ALU mov, cheap)
#define DUP_F32X2(d, f) \
    asm("mov.b64 %0, {%1, %1};" : "=l"(d) : "f"(f))

__device__ __forceinline__ float2 unpack_f32x2(unsigned long long v) {
    float2 r;
    r.x = __uint_as_float((unsigned int)(v & 0xffffffffull));
    r.y = __uint_as_float((unsigned int)(v >> 32));
    return r;
}

__device__ __forceinline__ int load_idx(const void* p, long long i, int is64) {
    if (is64) return (int)(((const long long*)p)[i]);
    return ((const int*)p)[i];
}

// ---------------- CSR build ----------------
__global__ void __launch_bounds__(256) k_zero(const void* __restrict__ ei, int n) {
    int i = blockIdx.x * blockDim.x + threadIdx.x;
    if (i < n) { g_cnt[i] = 0; g_fill[i] = 0; }
    if (blockIdx.x == 0 && threadIdx.x < 32) {
        int lane = threadIdx.x;
        const long long* p = (const long long*)ei;
        long long v = p[lane];
        unsigned ok = __ballot_sync(0xffffffffu, v >= 0 && v < n);
        if (lane == 0) g_is64 = (ok == 0xffffffffu) ? 1 : 0;
    }
}

__global__ void __launch_bounds__(256) k_hist(const void* __restrict__ ei, int E, int n) {
    int e = blockIdx.x * blockDim.x + threadIdx.x;
    int is64 = g_is64;
    if (e < E) {
        int d = load_idx(ei, (long long)E + e, is64);
        if (d >= 0 && d < n) atomicAdd(&g_cnt[d], 1);
    }
}

__global__ void __launch_bounds__(SCB) k_blocksum(int n) {
    __shared__ int sw[SCB / 32];
    int i = blockIdx.x * SCB + threadIdx.x;
    int c = (i < n) ? g_cnt[i] : 0;
#pragma unroll
    for (int off = 16; off; off >>= 1) c += __shfl_down_sync(0xffffffffu, c, off);
    int lane = threadIdx.x & 31, wid = threadIdx.x >> 5;
    if (lane == 0) sw[wid] = c;
    __syncthreads();
    if (wid == 0) {
        int v = (lane < SCB / 32) ? sw[lane] : 0;
#pragma unroll
        for (int off = 16; off; off >>= 1) v += __shfl_down_sync(0xffffffffu, v, off);
        if (lane == 0) g_bsum[blockIdx.x] = v;
    }
}

__global__ void __launch_bounds__(SCB) k_blockscan(int nb, int n) {
    __shared__ int sb[NSB];
    __shared__ int sw[SCB / 32];
    int t = threadIdx.x;
    for (int i = t; i < nb; i += SCB) sb[i] = g_bsum[i];
    __syncthreads();
    if (t == 0) {
        int run = 0;
        for (int i = 0; i < nb; i++) { int c = sb[i]; sb[i] = run; run += c; }
        if (blockIdx.x == 0) g_rowptr[n] = run;
    }
    __syncthreads();

    int i = blockIdx.x * SCB + t;
    int lane = t & 31, wid = t >> 5;
    int c = (i < n) ? g_cnt[i] : 0;
    int v = c;
#pragma unroll
    for (int off = 1; off < 32; off <<= 1) {
        int tv = __shfl_up_sync(0xffffffffu, v, off);
        if (lane >= off) v += tv;
    }
    if (lane == 31) sw[wid] = v;
    __syncthreads();
    if (wid == 0) {
        int w = (lane < SCB / 32) ? sw[lane] : 0;
#pragma unroll
        for (int off = 1; off < SCB / 32; off <<= 1) {
            int tv = __shfl_up_sync(0xffffffffu, w, off);
            if (lane >= off) w += tv;
        }
        if (lane < SCB / 32) sw[lane] = w;
    }
    __syncthreads();
    int base = sb[blockIdx.x] + (wid ? sw[wid - 1] : 0);
    if (i < n) {
        g_rowptr[i] = base + v - c;                 // exclusive
        g_dinv[i]   = rsqrtf((float)(c + 1));       // +1 self-loop
    }
}

__global__ void __launch_bounds__(256) k_scatter(const void* __restrict__ ei, int E, int n) {
    int e = blockIdx.x * blockDim.x + threadIdx.x;
    int is64 = g_is64;
    if (e < E) {
        int s = load_idx(ei, e, is64);
        int d = load_idx(ei, (long long)E + e, is64);
        if (s >= 0 && s < n && d >= 0 && d < n) {
            int p = g_rowptr[d] + atomicAdd(&g_fill[d], 1);
            g_col[p] = s;
        }
    }
}

// ---------------- fp32x2 tiled GEMM: C[M,N] = A[M,K] @ W[K,N] (+bias) ----------------
// (measured-best config: 64-row tile, 4 cols/thread, DUP+FMA2, 2 CTAs/SM)
// ldw/ldc: row strides of W and C (allow column-block views of wider matrices).
template <int K, int N, bool HASBIAS>
__device__ __forceinline__ void gemm_body(const float* __restrict__ A,
                                          const float* __restrict__ W, int ldw,
                                          const float* __restrict__ bias,
                                          float* __restrict__ C, int ldc,
                                          int M, int bx) {
    constexpr int CG  = N / 4;       // float4 column groups
    constexpr int RG  = 256 / CG;    // row groups
    constexpr int RPT = 64 / RG;     // rows per thread
    __shared__ __align__(16) float sA[64 * 32];
    __shared__ __align__(16) float sW[32 * N];

    int t    = threadIdx.x;
    int row0 = bx * 64;
    int colg = t % CG;
    int ty   = t / CG;

    unsigned long long acc[RPT][2];
#pragma unroll
    for (int i = 0; i < RPT; i++) { acc[i][0] = 0ull; acc[i][1] = 0ull; }

    for (int k0 = 0; k0 < K; k0 += 32) {
        // A tile: 64 rows x 32 k-floats = 512 float4
#pragma unroll
        for (int i = 0; i < 2; i++) {
            int q  = t + i * 256;
            int rr = q >> 3;
            int kq = (q & 7) * 4;
            int gr = row0 + rr;
            float4 val = make_float4(0.f, 0.f, 0.f, 0.f);
            if (gr < M) val = *(const float4*)(A + (size_t)gr * K + k0 + kq);
            *(float4*)(sA + rr * 32 + kq) = val;
        }
        // W tile: 32 rows x N floats (row stride ldw)
        constexpr int WQ = (32 * N) / 1024;  // float4 loads per thread
#pragma unroll
        for (int i = 0; i < WQ; i++) {
            int q  = t + i * 256;
            int kk = (q * 4) / N;
            int c  = (q * 4) % N;
            ((float4*)sW)[q] = *(const float4*)(W + (size_t)(k0 + kk) * ldw + c);
        }
        __syncthreads();

#pragma unroll
        for (int kk = 0; kk < 32; kk++) {
            ulonglong2 w2 = *(const ulonglong2*)(sW + kk * N + colg * 4);
#pragma unroll
            for (int i = 0; i < RPT; i++) {
                float a = sA[(ty + i * RG) * 32 + kk];
                unsigned long long a2;
                DUP_F32X2(a2, a);
                FMA_F32X2(acc[i][0], a2, w2.x);
                FMA_F32X2(acc[i][1], a2, w2.y);
            }
        }
        __syncthreads();
    }

    float4 bv = make_float4(0.f, 0.f, 0.f, 0.f);
    if constexpr (HASBIAS) bv = ((const float4*)bias)[colg];
#pragma unroll
    for (int i = 0; i < RPT; i++) {
        int gr = row0 + ty + i * RG;
        if (gr < M) {
            float2 lo = unpack_f32x2(acc[i][0]);
            float2 hi = unpack_f32x2(acc[i][1]);
            float4 r = make_float4(lo.x, lo.y, hi.x, hi.y);
            if constexpr (HASBIAS) { r.x += bv.x; r.y += bv.y; r.z += bv.z; r.w += bv.w; }
            *(float4*)(C + (size_t)gr * ldc + colg * 4) = r;
        }
    }
}

__global__ void __launch_bounds__(256, 2) k_gemm1(const float* __restrict__ x,
                                                  const float* __restrict__ W1, int M) {
    gemm_body<128, 128, false>(x, W1, 128, nullptr, g_h1, 128, M, blockIdx.x);
}
__global__ void __launch_bounds__(256, 2) k_gemm2(const float* __restrict__ W2, int M) {
    gemm_body<128, 64, false>(g_z1, W2, 64, nullptr, g_h2, 64, M, blockIdx.x);
}
// u/v projections for one 64-column half (colOff in {0,64}).
// First halfgrid blocks -> u columns, rest -> v columns.
__global__ void __launch_bounds__(256, 2) k_gemm_uv_half(const float* __restrict__ Wa,
                                                         const float* __restrict__ ba,
                                                         int colOff, int M, int halfgrid) {
    if ((int)blockIdx.x < halfgrid) {
        gemm_body<64, 64, true>(g_z2, Wa + colOff, 128, ba + colOff,
                                g_u + colOff, 128, M, blockIdx.x);
    } else {
        gemm_body<64, 64, false>(g_z2, Wa + 64 * 128 + colOff, 128, nullptr,
                                 g_v + colOff, 128, M, blockIdx.x - halfgrid);
    }
}

// ---------------- GCN aggregation: warp per node, CSR gather ------
template <int F, bool RELU>
__device__ __forceinline__ void agg_body(const float* __restrict__ H,
                                         const float* __restrict__ bias,
                                         float* __restrict__ out, int n) {
    int warp = (blockIdx.x * blockDim.x + threadIdx.x) >> 5;
    if (warp >= n) return;
    int lane = threadIdx.x & 31;
    float dn = g_dinv[warp];

    if constexpr (F == 128) {
        const float4* __restrict__ H4 = (const float4*)H;
        float4 h = H4[(size_t)warp * 32 + lane];
        float ax = h.x * dn, ay = h.y * dn, az = h.z * dn, aw = h.w * dn;

        int start = g_rowptr[warp];
        int end   = g_rowptr[warp + 1];
        int e     = start;
        for (; e + 3 < end; e += 4) {
            int   s0 = g_col[e],     s1 = g_col[e + 1];
            int   s2 = g_col[e + 2], s3 = g_col[e + 3];
            float w0 = g_dinv[s0], w1 = g_dinv[s1];
            float w2 = g_dinv[s2], w3 = g_dinv[s3];
            float4 h0 = H4[(size_t)s0 * 32 + lane];
            float4 h1 = H4[(size_t)s1 * 32 + lane];
            float4 h2 = H4[(size_t)s2 * 32 + lane];
            float4 h3 = H4[(size_t)s3 * 32 + lane];
            ax = fmaf(h0.x, w0, ax); ay = fmaf(h0.y, w0, ay);
            az = fmaf(h0.z, w0, az); aw = fmaf(h0.w, w0, aw);
            ax = fmaf(h1.x, w1, ax); ay = fmaf(h1.y, w1, ay);
            az = fmaf(h1.z, w1, az); aw = fmaf(h1.w, w1, aw);
            ax = fmaf(h2.x, w2, ax); ay = fmaf(h2.y, w2, ay);
            az = fmaf(h2.z, w2, az); aw = fmaf(h2.w, w2, aw);
            ax = fmaf(h3.x, w3, ax); ay = fmaf(h3.y, w3, ay);
            az = fmaf(h3.z, w3, az); aw = fmaf(h3.w, w3, aw);
        }
        for (; e < end; e++) {
            int   s0 = g_col[e];
            float w0 = g_dinv[s0];
            float4 h0 = H4[(size_t)s0 * 32 + lane];
            ax = fmaf(h0.x, w0, ax); ay = fmaf(h0.y, w0, ay);
            az = fmaf(h0.z, w0, az); aw = fmaf(h0.w, w0, aw);
        }

        float4 b = ((const float4*)bias)[lane];
        float4 r;
        r.x = ax * dn + b.x;
        r.y = ay * dn + b.y;
        r.z = az * dn + b.z;
        r.w = aw * dn + b.w;
        if constexpr (RELU) {
            r.x = fmaxf(r.x, 0.f); r.y = fmaxf(r.y, 0.f);
            r.z = fmaxf(r.z, 0.f); r.w = fmaxf(r.w, 0.f);
        }
        ((float4*)out)[(size_t)warp * 32 + lane] = r;
    } else {
        const float2* __restrict__ H2 = (const float2*)H;
        float2 h = H2[(size_t)warp * 32 + lane];
        float ax = h.x * dn, ay = h.y * dn;

        int start = g_rowptr[warp];
        int end   = g_rowptr[warp + 1];
        int e     = start;
        for (; e + 3 < end; e += 4) {
            int   s0 = g_col[e],     s1 = g_col[e + 1];
            int   s2 = g_col[e + 2], s3 = g_col[e + 3];
            float w0 = g_dinv[s0], w1 = g_dinv[s1];
            float w2 = g_dinv[s2], w3 = g_dinv[s3];
            float2 h0 = H2[(size_t)s0 * 32 + lane];
            float2 h1 = H2[(size_t)s1 * 32 + lane];
            float2 h2 = H2[(size_t)s2 * 32 + lane];
            float2 h3 = H2[(size_t)s3 * 32 + lane];
            ax = fmaf(h0.x, w0, ax); ay = fmaf(h0.y, w0, ay);
            ax = fmaf(h1.x, w1, ax); ay = fmaf(h1.y, w1, ay);
            ax = fmaf(h2.x, w2, ax); ay = fmaf(h2.y, w2, ay);
            ax = fmaf(h3.x, w3, ax); ay = fmaf(h3.y, w3, ay);
        }
        for (; e < end; e++) {
            int   s0 = g_col[e];
            float w0 = g_dinv[s0];
            float2 h0 = H2[(size_t)s0 * 32 + lane];
            ax = fmaf(h0.x, w0, ax); ay = fmaf(h0.y, w0, ay);
        }

        float2 b = ((const float2*)bias)[lane];
        float2 r;
        r.x = ax * dn + b.x;
        r.y = ay * dn + b.y;
        if constexpr (RELU) { r.x = fmaxf(r.x, 0.f); r.y = fmaxf(r.y, 0.f); }
        ((float2*)out)[(size_t)warp * 32 + lane] = r;
    }
}

__global__ void __launch_bounds__(256) k_agg1(const float* __restrict__ b1, int n) {
    agg_body<128, true>(g_h1, b1, g_z1, n);
}
__global__ void __launch_bounds__(256) k_agg2(const float* __restrict__ b2, int n) {
    agg_body<64, false>(g_h2, b2, g_z2, n);
}

// ---------------- decoder, split over hidden-dim halves --------------------------
// Half H (colOff in {0,64}): partial = sum_{j in half} relu(u[s][j]+v[d][j])*Wb[j].
// FIRST stores the partial; SECOND adds the stored partial + bb and writes out.
template <bool FIRST>
__device__ __forceinline__ void decode_half(const void* __restrict__ pe,
                                            const void* __restrict__ ne,
                                            const float* __restrict__ Wb,
                                            const float* __restrict__ bb,
                                            float* __restrict__ out,
                                            int P, int colOff) {
    int warp = (blockIdx.x * blockDim.x + threadIdx.x) >> 5;
    if (warp >= 2 * P) return;
    int lane = threadIdx.x & 31;
    int is64 = g_is64;
    int s, d;
    if (warp < P) {
        s = load_idx(pe, warp, is64);
        d = load_idx(pe, (long long)P + warp, is64);
    } else {
        int q = warp - P;
        s = load_idx(ne, q, is64);
        d = load_idx(ne, (long long)P + q, is64);
    }

    const float2* __restrict__ U = (const float2*)(g_u + colOff);
    const float2* __restrict__ V = (const float2*)(g_v + colOff);
    float2 uu = U[(size_t)s * 64 + lane];
    float2 vv = V[(size_t)d * 64 + lane];
    float2 wb = ((const float2*)(Wb + colOff))[lane];
    float p = fmaxf(uu.x + vv.x, 0.f) * wb.x
            + fmaxf(uu.y + vv.y, 0.f) * wb.y;
#pragma unroll
    for (int off = 16; off; off >>= 1) p += __shfl_xor_sync(0xffffffffu, p, off);
    if (lane == 0) {
        if constexpr (FIRST) g_pp[warp] = p;
        else                 out[warp] = p + g_pp[warp] + bb[0];
    }
}

__global__ void __launch_bounds__(256) k_decode0(const void* __restrict__ pe,
                                                 const void* __restrict__ ne,
                                                 const float* __restrict__ Wb,
                                                 int P) {
    decode_half<true>(pe, ne, Wb, nullptr, nullptr, P, 0);
}
__global__ void __launch_bounds__(256) k_decode1(const void* __restrict__ pe,
                                                 const void* __restrict__ ne,
                                                 const float* __restrict__ Wb,
                                                 const float* __restrict__ bb,
                                                 float* __restrict__ out, int P) {
    decode_half<false>(pe, ne, Wb, bb, out, P, 64);
}
// fallback single-pass decode (used only if P exceeds PMAX)
__global__ void __launch_bounds__(256) k_decode(const void* __restrict__ pe,
                                                const void* __restrict__ ne,
                                                const float* __restrict__ Wb,
                                                const float* __restrict__ bb,
                                                float* __restrict__ out, int P) {
    int warp = (blockIdx.x * blockDim.x + threadIdx.x) >> 5;
    if (warp >= 2 * P) return;
    int lane = threadIdx.x & 31;
    int is64 = g_is64;
    int s, d;
    if (warp < P) {
        s = load_idx(pe, warp, is64);
        d = load_idx(pe, (long long)P + warp, is64);
    } else {
        int q = warp - P;
        s = load_idx(ne, q, is64);
        d = load_idx(ne, (long long)P + q, is64);
    }
    float4 uu = ((const float4*)g_u)[(size_t)s * 32 + lane];
    float4 vv = ((const float4*)g_v)[(size_t)d * 32 + lane];
    float4 wb = ((const float4*)Wb)[lane];
    float p = fmaxf(uu.x + vv.x, 0.f) * wb.x
            + fmaxf(uu.y + vv.y, 0.f) * wb.y
            + fmaxf(uu.z + vv.z, 0.f) * wb.z
            + fmaxf(uu.w + vv.w, 0.f) * wb.w;
#pragma unroll
    for (int off = 16; off; off >>= 1) p += __shfl_xor_sync(0xffffffffu, p, off);
    if (lane == 0) out[warp] = p + bb[0];
}

// ---------------- launch: CSR||gemm1 fork-join + uv/decode column pipelining ----
extern "C" void kernel_launch(void* const* d_in, const int* in_sizes, int n_in,
                              void* d_out, int out_size) {
    const float* x  = (const float*)d_in[0];
    const void*  ei = d_in[1];
    const void*  pe = d_in[2];
    const void*  ne = d_in[3];
    const float* W1 = (const float*)d_in[4];
    const float* b1 = (const float*)d_in[5];
    const float* W2 = (const float*)d_in[6];
    const float* b2 = (const float*)d_in[7];
    const float* Wa = (const float*)d_in[8];
    const float* ba = (const float*)d_in[9];
    const float* Wb = (const float*)d_in[10];
    const float* bb = (const float*)d_in[11];
    float* out = (float*)d_out;

    int n = in_sizes[0] / 128;
    int E = in_sizes[1] / 2;
    int P = in_sizes[2] / 2;

    int nb        = (n + SCB - 1) / SCB;
    int gemm_grid = (n + 63) / 64;
    int agg_grid  = (n * 32 + 255) / 256;
    int dec_grid  = (2 * P * 32 + 255) / 256;

    // One-time resource creation (handles cached; per-call work identical).
    static cudaStream_t side = nullptr;
    static cudaEvent_t  evFork = nullptr, evJoin = nullptr;
    static cudaEvent_t  evUV0 = nullptr, evD0 = nullptr;
    if (side == nullptr) {
        cudaStreamCreateWithFlags(&side, cudaStreamNonBlocking);
        cudaEventCreateWithFlags(&evFork, cudaEventDisableTiming);
        cudaEventCreateWithFlags(&evJoin, cudaEventDisableTiming);
        cudaEventCreateWithFlags(&evUV0, cudaEventDisableTiming);
        cudaEventCreateWithFlags(&evD0, cudaEventDisableTiming);
    }

    // ---- fork: CSR (side) || gemm1 (main) ----
    cudaEventRecord(evFork, 0);
    cudaStreamWaitEvent(side, evFork, 0);

    k_zero<<<(n + 255) / 256, 256, 0, side>>>(ei, n);          // idx 0
    k_hist<<<(E + 255) / 256, 256, 0, side>>>(ei, E, n);       // idx 1
    k_blocksum<<<nb, SCB, 0, side>>>(n);                       // idx 2
    k_gemm1<<<gemm_grid, 256>>>(x, W1, n);                     // idx 3 <- profiled
    k_blockscan<<<nb, SCB, 0, side>>>(nb, n);                  // idx 4
    k_scatter<<<(E + 255) / 256, 256, 0, side>>>(ei, E, n);    // idx 5

    cudaEventRecord(evJoin, side);
    cudaStreamWaitEvent(0, evJoin, 0);

    // ---- serial layer chain (measured-best) ----
    k_agg1<<<agg_grid, 256>>>(b1, n);
    k_gemm2<<<gemm_grid, 256>>>(W2, n);
    k_agg2<<<agg_grid, 256>>>(b2, n);

    if (P <= PMAX) {
        // uv columns 0-63, then decode half0 (side) || uv columns 64-127 (main)
        k_gemm_uv_half<<<2 * gemm_grid, 256>>>(Wa, ba, 0, n, gemm_grid);
        cudaEventRecord(evUV0, 0);
        cudaStreamWaitEvent(side, evUV0, 0);
        k_decode0<<<dec_grid, 256, 0, side>>>(pe, ne, Wb, P);
        k_gemm_uv_half<<<2 * gemm_grid, 256>>>(Wa, ba, 64, n, gemm_grid);
        cudaEventRecord(evD0, side);
        cudaStreamWaitEvent(0, evD0, 0);
        k_decode1<<<dec_grid, 256>>>(pe, ne, Wb, bb, out, P);
    } else {
        k_gemm_uv_half<<<2 * gemm_grid, 256>>>(Wa, ba, 0, n, gemm_grid);
        k_gemm_uv_half<<<2 * gemm_grid, 256>>>(Wa, ba, 64, n, gemm_grid);
        k_decode<<<dec_grid, 256>>>(pe, ne, Wb, bb, out, P);
    }
}

// round 16
// speedup vs baseline: 1.2008x; 1.2008x over previous
#include <cuda_runtime.h>
#include <cstdint>
#include <math.h>

// Problem-size constants (fixed by the dataset)
#define NN   50000
#define EMAX 800000
#define SCB  512                    // scan block size
#define NSB  ((NN + SCB - 1) / SCB) // number of scan blocks (98)

// ---------------- scratch (device globals; no runtime allocation) ----------------
__device__ __align__(16) float g_h1[NN * 128];   // x @ W1
__device__ __align__(16) float g_z1[NN * 128];   // relu(agg(h1) + b1)
__device__ __align__(16) float g_h2[NN * 64];    // z1 @ W2
__device__ __align__(16) float g_z2[NN * 64];    // agg(h2) + b2
__device__ __align__(16) float g_u [NN * 128];   // z2 @ Wa[0:64]  + ba
__device__ __align__(16) float g_v [NN * 128];   // z2 @ Wa[64:128]
__device__ __align__(16) float g_dinv[NN];
__device__ __align__(16) int   g_cnt [NN];
__device__ __align__(16) int   g_fill[NN];
__device__ __align__(16) int   g_rowptr[NN + 1];
__device__ __align__(16) int   g_col[EMAX];
__device__ __align__(16) int   g_bsum[NSB + 1];
__device__ int g_is64;   // 1 if index arrays are int64, 0 if int32

// packed fp32x2 FMA: d = a*b + d (elementwise on 64-bit register pairs)
#define FMA_F32X2(d, a, b) \
    asm("fma.rn.f32x2 %0, %1, %2, %0;" : "+l"(d) : "l"(a), "l"(b))
// pack one float into both halves of a 64-bit register pair (ALU mov, cheap)
#define DUP_F32X2(d, f) \
    asm("mov.b64 %0, {%1, %1};" : "=l"(d) : "f"(f))

__device__ __forceinline__ float2 unpack_f32x2(unsigned long long v) {
    float2 r;
    r.x = __uint_as_float((unsigned int)(v & 0xffffffffull));
    r.y = __uint_as_float((unsigned int)(v >> 32));
    return r;
}

__device__ __forceinline__ int load_idx(const void* p, long long i, int is64) {
    if (is64) return (int)(((const long long*)p)[i]);
    return ((const int*)p)[i];
}

// ---------------- CSR build ----------------
// zero + dtype detection fused (block 0 / warp 0 detects)
__global__ void __launch_bounds__(256) k_zero(const void* __restrict__ ei, int n) {
    int i = blockIdx.x * blockDim.x + threadIdx.x;
    if (i < n) { g_cnt[i] = 0; g_fill[i] = 0; }
    if (blockIdx.x == 0 && threadIdx.x < 32) {
        int lane = threadIdx.x;
        const long long* p = (const long long*)ei;
        long long v = p[lane];
        unsigned ok = __ballot_sync(0xffffffffu, v >= 0 && v < n);
        if (lane == 0) g_is64 = (ok == 0xffffffffu) ? 1 : 0;
    }
}

__global__ void __launch_bounds__(256) k_hist(const void* __restrict__ ei, int E, int n) {
    int e = blockIdx.x * blockDim.x + threadIdx.x;
    int is64 = g_is64;
    if (e < E) {
        int d = load_idx(ei, (long long)E + e, is64);
        if (d >= 0 && d < n) atomicAdd(&g_cnt[d], 1);
    }
}

__global__ void __launch_bounds__(SCB) k_blocksum(int n) {
    __shared__ int sw[SCB / 32];
    int i = blockIdx.x * SCB + threadIdx.x;
    int c = (i < n) ? g_cnt[i] : 0;
#pragma unroll
    for (int off = 16; off; off >>= 1) c += __shfl_down_sync(0xffffffffu, c, off);
    int lane = threadIdx.x & 31, wid = threadIdx.x >> 5;
    if (lane == 0) sw[wid] = c;
    __syncthreads();
    if (wid == 0) {
        int v = (lane < SCB / 32) ? sw[lane] : 0;
#pragma unroll
        for (int off = 16; off; off >>= 1) v += __shfl_down_sync(0xffffffffu, v, off);
        if (lane == 0) g_bsum[blockIdx.x] = v;
    }
}

// per-block exclusive scan; each block redundantly scans the (<=98) block sums
__global__ void __launch_bounds__(SCB) k_blockscan(int nb, int n) {
    __shared__ int sb[NSB];
    __shared__ int sw[SCB / 32];
    int t = threadIdx.x;
    for (int i = t; i < nb; i += SCB) sb[i] = g_bsum[i];
    __syncthreads();
    if (t == 0) {
        int run = 0;
        for (int i = 0; i < nb; i++) { int c = sb[i]; sb[i] = run; run += c; }
        if (blockIdx.x == 0) g_rowptr[n] = run;
    }
    __syncthreads();

    int i = blockIdx.x * SCB + t;
    int lane = t & 31, wid = t >> 5;
    int c = (i < n) ? g_cnt[i] : 0;
    int v = c;
#pragma unroll
    for (int off = 1; off < 32; off <<= 1) {
        int tv = __shfl_up_sync(0xffffffffu, v, off);
        if (lane >= off) v += tv;
    }
    if (lane == 31) sw[wid] = v;
    __syncthreads();
    if (wid == 0) {
        int w = (lane < SCB / 32) ? sw[lane] : 0;
#pragma unroll
        for (int off = 1; off < SCB / 32; off <<= 1) {
            int tv = __shfl_up_sync(0xffffffffu, w, off);
            if (lane >= off) w += tv;
        }
        if (lane < SCB / 32) sw[lane] = w;
    }
    __syncthreads();
    int base = sb[blockIdx.x] + (wid ? sw[wid - 1] : 0);
    if (i < n) {
        g_rowptr[i] = base + v - c;                 // exclusive
        g_dinv[i]   = rsqrtf((float)(c + 1));       // +1 self-loop
    }
}

__global__ void __launch_bounds__(256) k_scatter(const void* __restrict__ ei, int E, int n) {
    int e = blockIdx.x * blockDim.x + threadIdx.x;
    int is64 = g_is64;
    if (e < E) {
        int s = load_idx(ei, e, is64);
        int d = load_idx(ei, (long long)E + e, is64);
        if (s >= 0 && s < n && d >= 0 && d < n) {
            int p = g_rowptr[d] + atomicAdd(&g_fill[d], 1);
            g_col[p] = s;
        }
    }
}

// ---------------- fp32x2 tiled GEMM: C[M,N] = A[M,K] @ W[K,N] (+bias) ----------------
// (measured-best config: 64-row tile, 4 cols/thread, DUP+FMA2, 2 CTAs/SM)
template <int K, int N, bool HASBIAS>
__device__ __forceinline__ void gemm_body(const float* __restrict__ A,
                                          const float* __restrict__ W,
                                          const float* __restrict__ bias,
                                          float* __restrict__ C, int M, int bx) {
    constexpr int CG  = N / 4;       // float4 column groups
    constexpr int RG  = 256 / CG;    // row groups
    constexpr int RPT = 64 / RG;     // rows per thread
    __shared__ __align__(16) float sA[64 * 32];
    __shared__ __align__(16) float sW[32 * N];

    int t    = threadIdx.x;
    int row0 = bx * 64;
    int colg = t % CG;
    int ty   = t / CG;

    unsigned long long acc[RPT][2];
#pragma unroll
    for (int i = 0; i < RPT; i++) { acc[i][0] = 0ull; acc[i][1] = 0ull; }

    for (int k0 = 0; k0 < K; k0 += 32) {
        // A tile: 64 rows x 32 k-floats = 512 float4
#pragma unroll
        for (int i = 0; i < 2; i++) {
            int q  = t + i * 256;
            int rr = q >> 3;
            int kq = (q & 7) * 4;
            int gr = row0 + rr;
            float4 val = make_float4(0.f, 0.f, 0.f, 0.f);
            if (gr < M) val = *(const float4*)(A + (size_t)gr * K + k0 + kq);
            *(float4*)(sA + rr * 32 + kq) = val;
        }
        // W tile: 32 rows x N floats
        constexpr int WQ = (32 * N) / 1024;  // float4 loads per thread
#pragma unroll
        for (int i = 0; i < WQ; i++) {
            int q = t + i * 256;
            ((float4*)sW)[q] = ((const float4*)(W + (size_t)k0 * N))[q];
        }
        __syncthreads();

#pragma unroll
        for (int kk = 0; kk < 32; kk++) {
            ulonglong2 w2 = *(const ulonglong2*)(sW + kk * N + colg * 4);
#pragma unroll
            for (int i = 0; i < RPT; i++) {
                float a = sA[(ty + i * RG) * 32 + kk];
                unsigned long long a2;
                DUP_F32X2(a2, a);
                FMA_F32X2(acc[i][0], a2, w2.x);
                FMA_F32X2(acc[i][1], a2, w2.y);
            }
        }
        __syncthreads();
    }

    float4 bv = make_float4(0.f, 0.f, 0.f, 0.f);
    if constexpr (HASBIAS) bv = ((const float4*)bias)[colg];
#pragma unroll
    for (int i = 0; i < RPT; i++) {
        int gr = row0 + ty + i * RG;
        if (gr < M) {
            float2 lo = unpack_f32x2(acc[i][0]);
            float2 hi = unpack_f32x2(acc[i][1]);
            float4 r = make_float4(lo.x, lo.y, hi.x, hi.y);
            if constexpr (HASBIAS) { r.x += bv.x; r.y += bv.y; r.z += bv.z; r.w += bv.w; }
            *(float4*)(C + (size_t)gr * N + colg * 4) = r;
        }
    }
}

__global__ void __launch_bounds__(256, 2) k_gemm1(const float* __restrict__ x,
                                                  const float* __restrict__ W1, int M) {
    gemm_body<128, 128, false>(x, W1, nullptr, g_h1, M, blockIdx.x);
}
__global__ void __launch_bounds__(256, 2) k_gemm2(const float* __restrict__ W2, int M) {
    gemm_body<128, 64, false>(g_z1, W2, nullptr, g_h2, M, blockIdx.x);
}
// u and v projections in one launch: first half of blocks -> u, second -> v
__global__ void __launch_bounds__(256, 2) k_gemm_uv(const float* __restrict__ Wa,
                                                    const float* __restrict__ ba,
                                                    int M, int halfgrid) {
    if ((int)blockIdx.x < halfgrid) {
        gemm_body<64, 128, true>(g_z2, Wa, ba, g_u, M, blockIdx.x);
    } else {
        gemm_body<64, 128, false>(g_z2, Wa + 64 * 128, nullptr, g_v, M,
                                  blockIdx.x - halfgrid);
    }
}

// ---------------- GCN aggregation: warp per node, CSR gather ------
template <int F, bool RELU>
__device__ __forceinline__ void agg_body(const float* __restrict__ H,
                                         const float* __restrict__ bias,
                                         float* __restrict__ out, int n) {
    int warp = (blockIdx.x * blockDim.x + threadIdx.x) >> 5;
    if (warp >= n) return;
    int lane = threadIdx.x & 31;
    float dn = g_dinv[warp];

    if constexpr (F == 128) {
        const float4* __restrict__ H4 = (const float4*)H;
        float4 h = H4[(size_t)warp * 32 + lane];
        float ax = h.x * dn, ay = h.y * dn, az = h.z * dn, aw = h.w * dn;

        int start = g_rowptr[warp];
        int end   = g_rowptr[warp + 1];
        int e     = start;
        for (; e + 3 < end; e += 4) {
            int   s0 = g_col[e],     s1 = g_col[e + 1];
            int   s2 = g_col[e + 2], s3 = g_col[e + 3];
            float w0 = g_dinv[s0], w1 = g_dinv[s1];
            float w2 = g_dinv[s2], w3 = g_dinv[s3];
            float4 h0 = H4[(size_t)s0 * 32 + lane];
            float4 h1 = H4[(size_t)s1 * 32 + lane];
            float4 h2 = H4[(size_t)s2 * 32 + lane];
            float4 h3 = H4[(size_t)s3 * 32 + lane];
            ax = fmaf(h0.x, w0, ax); ay = fmaf(h0.y, w0, ay);
            az = fmaf(h0.z, w0, az); aw = fmaf(h0.w, w0, aw);
            ax = fmaf(h1.x, w1, ax); ay = fmaf(h1.y, w1, ay);
            az = fmaf(h1.z, w1, az); aw = fmaf(h1.w, w1, aw);
            ax = fmaf(h2.x, w2, ax); ay = fmaf(h2.y, w2, ay);
            az = fmaf(h2.z, w2, az); aw = fmaf(h2.w, w2, aw);
            ax = fmaf(h3.x, w3, ax); ay = fmaf(h3.y, w3, ay);
            az = fmaf(h3.z, w3, az); aw = fmaf(h3.w, w3, aw);
        }
        for (; e < end; e++) {
            int   s0 = g_col[e];
            float w0 = g_dinv[s0];
            float4 h0 = H4[(size_t)s0 * 32 + lane];
            ax = fmaf(h0.x, w0, ax); ay = fmaf(h0.y, w0, ay);
            az = fmaf(h0.z, w0, az); aw = fmaf(h0.w, w0, aw);
        }

        float4 b = ((const float4*)bias)[lane];
        float4 r;
        r.x = ax * dn + b.x;
        r.y = ay * dn + b.y;
        r.z = az * dn + b.z;
        r.w = aw * dn + b.w;
        if constexpr (RELU) {
            r.x = fmaxf(r.x, 0.f); r.y = fmaxf(r.y, 0.f);
            r.z = fmaxf(r.z, 0.f); r.w = fmaxf(r.w, 0.f);
        }
        ((float4*)out)[(size_t)warp * 32 + lane] = r;
    } else {
        const float2* __restrict__ H2 = (const float2*)H;
        float2 h = H2[(size_t)warp * 32 + lane];
        float ax = h.x * dn, ay = h.y * dn;

        int start = g_rowptr[warp];
        int end   = g_rowptr[warp + 1];
        int e     = start;
        for (; e + 3 < end; e += 4) {
            int   s0 = g_col[e],     s1 = g_col[e + 1];
            int   s2 = g_col[e + 2], s3 = g_col[e + 3];
            float w0 = g_dinv[s0], w1 = g_dinv[s1];
            float w2 = g_dinv[s2], w3 = g_dinv[s3];
            float2 h0 = H2[(size_t)s0 * 32 + lane];
            float2 h1 = H2[(size_t)s1 * 32 + lane];
            float2 h2 = H2[(size_t)s2 * 32 + lane];
            float2 h3 = H2[(size_t)s3 * 32 + lane];
            ax = fmaf(h0.x, w0, ax); ay = fmaf(h0.y, w0, ay);
            ax = fmaf(h1.x, w1, ax); ay = fmaf(h1.y, w1, ay);
            ax = fmaf(h2.x, w2, ax); ay = fmaf(h2.y, w2, ay);
            ax = fmaf(h3.x, w3, ax); ay = fmaf(h3.y, w3, ay);
        }
        for (; e < end; e++) {
            int   s0 = g_col[e];
            float w0 = g_dinv[s0];
            float2 h0 = H2[(size_t)s0 * 32 + lane];
            ax = fmaf(h0.x, w0, ax); ay = fmaf(h0.y, w0, ay);
        }

        float2 b = ((const float2*)bias)[lane];
        float2 r;
        r.x = ax * dn + b.x;
        r.y = ay * dn + b.y;
        if constexpr (RELU) { r.x = fmaxf(r.x, 0.f); r.y = fmaxf(r.y, 0.f); }
        ((float2*)out)[(size_t)warp * 32 + lane] = r;
    }
}

__global__ void __launch_bounds__(256) k_agg1(const float* __restrict__ b1, int n) {
    agg_body<128, true>(g_h1, b1, g_z1, n);
}
__global__ void __launch_bounds__(256) k_agg2(const float* __restrict__ b2, int n) {
    agg_body<64, false>(g_h2, b2, g_z2, n);
}

// ---------------- decoder: warp per pair; pred = relu(u[s]+v[d]) . Wb + bb ----------------
__global__ void __launch_bounds__(256) k_decode(const void* __restrict__ pe,
                                                const void* __restrict__ ne,
                                                const float* __restrict__ Wb,
                                                const float* __restrict__ bb,
                                                float* __restrict__ out, int P) {
    int warp = (blockIdx.x * blockDim.x + threadIdx.x) >> 5;
    if (warp >= 2 * P) return;
    int lane = threadIdx.x & 31;
    int is64 = g_is64;
    int s, d;
    if (warp < P) {
        s = load_idx(pe, warp, is64);
        d = load_idx(pe, (long long)P + warp, is64);
    } else {
        int q = warp - P;
        s = load_idx(ne, q, is64);
        d = load_idx(ne, (long long)P + q, is64);
    }

    float4 uu = ((const float4*)g_u)[(size_t)s * 32 + lane];
    float4 vv = ((const float4*)g_v)[(size_t)d * 32 + lane];
    float4 wb = ((const float4*)Wb)[lane];
    float p = fmaxf(uu.x + vv.x, 0.f) * wb.x
            + fmaxf(uu.y + vv.y, 0.f) * wb.y
            + fmaxf(uu.z + vv.z, 0.f) * wb.z
            + fmaxf(uu.w + vv.w, 0.f) * wb.w;
#pragma unroll
    for (int off = 16; off; off >>= 1) p += __shfl_xor_sync(0xffffffffu, p, off);
    if (lane == 0) out[warp] = p + bb[0];
}

// ---------------- launch: CSR build forked onto a side stream, overlapping gemm1 ----
extern "C" void kernel_launch(void* const* d_in, const int* in_sizes, int n_in,
                              void* d_out, int out_size) {
    const float* x  = (const float*)d_in[0];
    const void*  ei = d_in[1];
    const void*  pe = d_in[2];
    const void*  ne = d_in[3];
    const float* W1 = (const float*)d_in[4];
    const float* b1 = (const float*)d_in[5];
    const float* W2 = (const float*)d_in[6];
    const float* b2 = (const float*)d_in[7];
    const float* Wa = (const float*)d_in[8];
    const float* ba = (const float*)d_in[9];
    const float* Wb = (const float*)d_in[10];
    const float* bb = (const float*)d_in[11];
    float* out = (float*)d_out;

    int n = in_sizes[0] / 128;
    int E = in_sizes[1] / 2;
    int P = in_sizes[2] / 2;

    int nb        = (n + SCB - 1) / SCB;
    int gemm_grid = (n + 63) / 64;
    int agg_grid  = (n * 32 + 255) / 256;

    // One-time resource creation (handles cached; per-call work is identical,
    // so kernel_launch stays deterministic). During graph replay this is free.
    static cudaStream_t side = nullptr;
    static cudaEvent_t  evFork = nullptr, evJoin = nullptr;
    if (side == nullptr) {
        cudaStreamCreateWithFlags(&side, cudaStreamNonBlocking);
        cudaEventCreateWithFlags(&evFork, cudaEventDisableTiming);
        cudaEventCreateWithFlags(&evJoin, cudaEventDisableTiming);
    }

    // Fork: side stream inherits the main stream's current position.
    cudaEventRecord(evFork, 0);
    cudaStreamWaitEvent(side, evFork, 0);

    // CSR build on the side stream (independent of gemm1).
    k_zero<<<(n + 255) / 256, 256, 0, side>>>(ei, n);          // idx 0
    k_hist<<<(E + 255) / 256, 256, 0, side>>>(ei, E, n);       // idx 1
    k_blocksum<<<nb, SCB, 0, side>>>(n);                       // idx 2
    // gemm1 on the main stream, concurrent with the CSR chain.
    k_gemm1<<<gemm_grid, 256>>>(x, W1, n);                     // idx 3 <- profiled
    k_blockscan<<<nb, SCB, 0, side>>>(nb, n);                  // idx 4
    k_scatter<<<(E + 255) / 256, 256, 0, side>>>(ei, E, n);    // idx 5

    // Join: main stream waits for the CSR chain before aggregation.
    cudaEventRecord(evJoin, side);
    cudaStreamWaitEvent(0, evJoin, 0);

    k_agg1<<<agg_grid, 256>>>(b1, n);                          // idx 6
    k_gemm2<<<gemm_grid, 256>>>(W2, n);                        // idx 7
    k_agg2<<<agg_grid, 256>>>(b2, n);                          // idx 8
    k_gemm_uv<<<2 * gemm_grid, 256>>>(Wa, ba, n, gemm_grid);   // idx 9
    k_decode<<<(2 * P * 32 + 255) / 256, 256>>>(pe, ne, Wb, bb, out, P); // idx 10
}